// round 8
// baseline (speedup 1.0000x reference)
#include <cuda_runtime.h>
#include <math.h>
#include <stdint.h>

// ---------------------------------------------------------------- dims
constexpr int MDIM = 2048, KDIM = 2048, NDIM = 256;

// ---------------------------------------------------------------- tiling
constexpr int BM = 64, BN = 32, BK = 64;     // BK = 64 int8 per stage row
constexpr int NIT = KDIM / BK;               // 32
constexpr int THREADS = 256;                 // 8 warps: 4 (m) x 2 (n)
constexpr int STAGES = 6;                    // deep ring: cover L2 latency
constexpr int PREF = STAGES - 1;             // 5 stages in flight
constexpr int ROWB = 80;                     // padded row bytes (64 data + 16)
constexpr int ARR_A = 64 * ROWB;             // 5120 B per A digit array
constexpr int ARR_B = 32 * ROWB;             // 2560 B per B digit array
constexpr int OFF_A1 = 0;
constexpr int OFF_A2 = ARR_A;                // 5120
constexpr int OFF_B1 = 2 * ARR_A;            // 10240
constexpr int OFF_B2 = 2 * ARR_A + ARR_B;    // 12800
constexpr int STAGE_BYTES = 2 * ARR_A + 2 * ARR_B;   // 15360
constexpr int SMEM_BYTES = STAGES * STAGE_BYTES;     // 92160

// ---------------------------------------------------------------- scratch
__device__ int8_t g_WhxA1[MDIM * KDIM];
__device__ int8_t g_WhxA2[MDIM * KDIM];
__device__ int8_t g_WhhA1[MDIM * KDIM];
__device__ int8_t g_WhhA2[MDIM * KDIM];
__device__ int8_t g_WphA1[MDIM * KDIM];
__device__ int8_t g_WphA2[MDIM * KDIM];
__device__ int8_t g_xB1[NDIM * KDIM];
__device__ int8_t g_xB2[NDIM * KDIM];
__device__ int8_t g_h0B1[NDIM * KDIM];
__device__ int8_t g_h0B2[NDIM * KDIM];
__device__ int8_t g_h1B1[NDIM * KDIM];
__device__ int8_t g_h1B2[NDIM * KDIM];
__device__ float  g_c[MDIM * NDIM];
__device__ float  g_p[MDIM * NDIM];
__device__ int    g_maxbits[4];              // maxabs of Whx, Whh, Wph, x

// ---------------------------------------------------------------- helpers
__device__ __forceinline__ uint32_t smem_u32(const void* p) {
    uint32_t a;
    asm("{ .reg .u64 t; cvta.to.shared.u64 t, %1; cvt.u32.u64 %0, t; }"
        : "=r"(a) : "l"(p));
    return a;
}

__device__ __forceinline__ void mma_s8(int* c, const uint32_t* a,
                                       const uint32_t* b) {
    asm volatile(
        "mma.sync.aligned.m16n8k32.row.col.s32.s8.s8.s32 "
        "{%0,%1,%2,%3}, {%4,%5,%6,%7}, {%8,%9}, {%0,%1,%2,%3};"
        : "+r"(c[0]), "+r"(c[1]), "+r"(c[2]), "+r"(c[3])
        : "r"(a[0]), "r"(a[1]), "r"(a[2]), "r"(a[3]), "r"(b[0]), "r"(b[1]));
}

__device__ __forceinline__ void ldsm_x4(uint32_t* r, uint32_t addr) {
    asm volatile("ldmatrix.sync.aligned.m8n8.x4.shared.b16 {%0,%1,%2,%3}, [%4];"
                 : "=r"(r[0]), "=r"(r[1]), "=r"(r[2]), "=r"(r[3]) : "r"(addr));
}

__device__ __forceinline__ void cp16(uint32_t sdst, const void* gsrc) {
    asm volatile("cp.async.cg.shared.global [%0], [%1], 16;"
                 :: "r"(sdst), "l"(gsrc));
}

// quantize q in [-127,127] to two int8 digits: q ~= d1 + d2/256
__device__ __forceinline__ void quant2(float q, int8_t& d1, int8_t& d2) {
    float b1 = rintf(q);
    float b2 = rintf((q - b1) * 256.0f);
    b2 = fminf(fmaxf(b2, -127.0f), 127.0f);
    d1 = (int8_t)(int)b1;
    d2 = (int8_t)(int)b2;
}

// ---------------------------------------------------------------- prep
__global__ void reset_kernel() {
    if (threadIdx.x < 4) g_maxbits[threadIdx.x] = 0;
}

__global__ void maxabs_kernel(const float* __restrict__ w0,
                              const float* __restrict__ w1,
                              const float* __restrict__ w2,
                              const float* __restrict__ x) {
    const int t = blockIdx.y;
    const float* src = (t == 0) ? w0 : (t == 1) ? w1 : (t == 2) ? w2 : x;
    const int len = (t == 3) ? KDIM * NDIM : MDIM * KDIM;
    float m = 0.0f;
    for (int i = blockIdx.x * 256 + threadIdx.x; i < len; i += 2048 * 256)
        m = fmaxf(m, fabsf(src[i]));
    #pragma unroll
    for (int o = 16; o > 0; o >>= 1)
        m = fmaxf(m, __shfl_xor_sync(~0u, m, o));
    if ((threadIdx.x & 31) == 0)
        atomicMax(&g_maxbits[t], __float_as_int(m));
}

__global__ void quant_kernel(const float* __restrict__ w0,
                             const float* __restrict__ w1,
                             const float* __restrict__ w2,
                             const float* __restrict__ x) {
    const int t = blockIdx.y;
    const int len = (t == 3) ? KDIM * NDIM : MDIM * KDIM;
    const int i = blockIdx.x * 256 + threadIdx.x;
    if (i >= len) return;
    const float mx = fmaxf(__int_as_float(g_maxbits[t]), 1e-20f);
    const float iq = 127.0f / mx;
    int8_t d1, d2;
    if (t == 3) {
        const int k = i / NDIM, n = i % NDIM;
        quant2(x[i] * iq, d1, d2);
        g_xB1[(size_t)n * KDIM + k] = d1;
        g_xB2[(size_t)n * KDIM + k] = d2;
    } else {
        const float* w = (t == 0) ? w0 : (t == 1) ? w1 : w2;
        int8_t* o1 = (t == 0) ? g_WhxA1 : (t == 1) ? g_WhhA1 : g_WphA1;
        int8_t* o2 = (t == 0) ? g_WhxA2 : (t == 1) ? g_WhhA2 : g_WphA2;
        quant2(w[i] * iq, d1, d2);
        o1[i] = d1;
        o2[i] = d2;
    }
}

// step 1 (h0 = 0): h1 = tanh(c + bh), quantized + transposed to [N][K]
__global__ void first_step_kernel(const float* __restrict__ c,
                                  const float* __restrict__ bh,
                                  int8_t* __restrict__ outB1,
                                  int8_t* __restrict__ outB2) {
    const int i = blockIdx.x * 256 + threadIdx.x;
    if (i >= MDIM * NDIM) return;
    const int n = i >> 11, m = i & 2047;   // i = n*2048 + m
    const float v = tanhf(c[(size_t)m * NDIM + n] + bh[n]);
    int8_t d1, d2;
    quant2(v * 127.0f, d1, d2);
    outB1[i] = d1;
    outB2[i] = d2;
}

// ---------------------------------------------------------------- main GEMM
// D = sA*sB*(A1@B1 + (A1@B2 + A2@B1)/256), A = [M][K] s8x2, B = [N][K] s8x2
// mode 0: outF = D
// mode 1: outF = D + bias
// mode 2: v = tanh(D + addc + bias); quant2(v*127) stored TRANSPOSED [N][K]
__global__ void __launch_bounds__(THREADS) rnn_gemm(
    const int8_t* __restrict__ A1, const int8_t* __restrict__ A2,
    const int8_t* __restrict__ B1, const int8_t* __restrict__ B2,
    const int* __restrict__ maxA, const int* __restrict__ maxB,
    const float* __restrict__ addc, const float* __restrict__ bias,
    float* __restrict__ outF,
    int8_t* __restrict__ outB1, int8_t* __restrict__ outB2,
    int mode)
{
    extern __shared__ __align__(16) char sm[];
    const uint32_t sbase = smem_u32(sm);
    const int tid  = threadIdx.x;
    const int lane = tid & 31;
    const int wid  = tid >> 5;
    const int wm0  = (wid & 3) * 16;     // 4 warps in m (m16 each)
    const int wn0  = (wid >> 2) * 16;    // 2 warps in n (n16 each)
    const int m0   = blockIdx.y * BM;
    const int n0   = blockIdx.x * BN;

    const float sa  = __int_as_float(*maxA) * (1.0f / 127.0f);
    const float sb  = maxB ? __int_as_float(*maxB) * (1.0f / 127.0f)
                           : (1.0f / 127.0f);
    const float sAB = sa * sb;

    int C1[2][4] = {};
    int C2[2][4] = {};

    // ldmatrix lane offsets (bytes) — same mapping as validated R6/R7 kernels
    const uint32_t aoff = (uint32_t)((lane & 15) * ROWB + (lane >> 4) * 16);
    const uint32_t boff = (uint32_t)((lane & 7) * ROWB +
                                     ((lane >> 4) & 1) * 8 * ROWB +
                                     ((lane >> 3) & 1) * 16);

    // stage loader: 960 x 16B chunks, 3 per thread
    const int arow = tid >> 2;             // 0..63
    const int aq   = tid & 3;              // 0..3
    const int brow = (tid & 127) >> 2;     // 0..31
    auto issue_stage = [&](int it) {
        const int s  = it % STAGES;
        const int k0 = it * BK;
        const uint32_t st = sbase + s * STAGE_BYTES;
        cp16(st + OFF_A1 + arow * ROWB + aq * 16,
             A1 + (size_t)(m0 + arow) * KDIM + k0 + aq * 16);
        cp16(st + OFF_A2 + arow * ROWB + aq * 16,
             A2 + (size_t)(m0 + arow) * KDIM + k0 + aq * 16);
        const int8_t* gb = ((tid < 128) ? B1 : B2) +
                           (size_t)(n0 + brow) * KDIM + k0 + aq * 16;
        cp16(st + OFF_B1 + (uint32_t)(tid >> 7) * ARR_B + brow * ROWB + aq * 16,
             gb);
        asm volatile("cp.async.commit_group;" ::: "memory");
    };

    #pragma unroll
    for (int s = 0; s < PREF; ++s) issue_stage(s);

    for (int it = 0; it < NIT; ++it) {
        // groups issued: 0..it+PREF-1; allow PREF-1 pending => stage it done
        asm volatile("cp.async.wait_group %0;" :: "n"(PREF - 1) : "memory");
        __syncthreads();
        if (it + PREF < NIT) issue_stage(it + PREF);
        else asm volatile("cp.async.commit_group;" ::: "memory");

        const uint32_t st  = sbase + (it % STAGES) * STAGE_BYTES;
        const uint32_t sA1 = st + OFF_A1;
        const uint32_t sA2 = st + OFF_A2;
        const uint32_t sB1 = st + OFF_B1;
        const uint32_t sB2 = st + OFF_B2;

        #pragma unroll
        for (int kk = 0; kk < 2; ++kk) {
            const uint32_t kb = kk * 32;           // 32 int8 = one k32 chunk
            uint32_t a1f[4], a2f[4], b1f[4], b2f[4];
            ldsm_x4(a1f, sA1 + (uint32_t)(wm0 * ROWB) + kb + aoff);
            ldsm_x4(a2f, sA2 + (uint32_t)(wm0 * ROWB) + kb + aoff);
            ldsm_x4(b1f, sB1 + (uint32_t)(wn0 * ROWB) + kb + boff);
            ldsm_x4(b2f, sB2 + (uint32_t)(wn0 * ROWB) + kb + boff);
            #pragma unroll
            for (int nt = 0; nt < 2; ++nt) {
                mma_s8(C1[nt], a1f, &b1f[nt * 2]);
                mma_s8(C2[nt], a1f, &b2f[nt * 2]);
                mma_s8(C2[nt], a2f, &b1f[nt * 2]);
            }
        }
    }

    // ------------------------------------------------------------ epilogue
    if (mode == 2) {
        __syncthreads();    // done reading tile stages; reuse smem
        int8_t* th = (int8_t*)sm;              // [32 n][80] digit-1
        int8_t* tl = (int8_t*)sm + 32 * ROWB;  // [32 n][80] digit-2
        #pragma unroll
        for (int nt = 0; nt < 2; ++nt) {
            const int lr = wm0 + (lane >> 2);
            const int lc = wn0 + nt * 8 + 2 * (lane & 3);
            const int gm = m0 + lr, gn = n0 + lc;
            float2 c0 = *(const float2*)(addc + (size_t)gm * NDIM + gn);
            float2 c1 = *(const float2*)(addc + (size_t)(gm + 8) * NDIM + gn);
            float2 bv = *(const float2*)(bias + gn);
            float d00 = sAB * ((float)C1[nt][0] + (float)C2[nt][0] * (1.0f / 256.0f));
            float d01 = sAB * ((float)C1[nt][1] + (float)C2[nt][1] * (1.0f / 256.0f));
            float d10 = sAB * ((float)C1[nt][2] + (float)C2[nt][2] * (1.0f / 256.0f));
            float d11 = sAB * ((float)C1[nt][3] + (float)C2[nt][3] * (1.0f / 256.0f));
            float v00 = tanhf(d00 + c0.x + bv.x) * 127.0f;
            float v01 = tanhf(d01 + c0.y + bv.y) * 127.0f;
            float v10 = tanhf(d10 + c1.x + bv.x) * 127.0f;
            float v11 = tanhf(d11 + c1.y + bv.y) * 127.0f;
            int8_t h, l;
            quant2(v00, h, l); th[lc * ROWB + lr] = h;       tl[lc * ROWB + lr] = l;
            quant2(v01, h, l); th[(lc + 1) * ROWB + lr] = h; tl[(lc + 1) * ROWB + lr] = l;
            quant2(v10, h, l); th[lc * ROWB + lr + 8] = h;   tl[lc * ROWB + lr + 8] = l;
            quant2(v11, h, l); th[(lc + 1) * ROWB + lr + 8] = h;
                               tl[(lc + 1) * ROWB + lr + 8] = l;
        }
        __syncthreads();
        // writeout: 32 rows x 4 chunks x 2 arrays = 256 chunks, 1 per thread
        const int arr = tid >> 7;
        const int rq  = tid & 127;
        const int row = rq >> 2;
        const int q   = rq & 3;
        const int8_t* src = (arr == 0) ? th : tl;
        int8_t* dst = (arr == 0) ? outB1 : outB2;
        uint4 v = *(const uint4*)&src[row * ROWB + q * 16];
        *(uint4*)&dst[(size_t)(n0 + row) * KDIM + m0 + q * 16] = v;
    } else {
        #pragma unroll
        for (int nt = 0; nt < 2; ++nt) {
            const int lr = wm0 + (lane >> 2);
            const int lc = wn0 + nt * 8 + 2 * (lane & 3);
            const int gm = m0 + lr, gn = n0 + lc;
            float bx = 0.f, by = 0.f;
            if (mode == 1) {
                float2 bv = *(const float2*)(bias + gn);
                bx = bv.x; by = bv.y;
            }
            float2 o0, o1;
            o0.x = sAB * ((float)C1[nt][0] + (float)C2[nt][0] * (1.0f / 256.0f)) + bx;
            o0.y = sAB * ((float)C1[nt][1] + (float)C2[nt][1] * (1.0f / 256.0f)) + by;
            o1.x = sAB * ((float)C1[nt][2] + (float)C2[nt][2] * (1.0f / 256.0f)) + bx;
            o1.y = sAB * ((float)C1[nt][3] + (float)C2[nt][3] * (1.0f / 256.0f)) + by;
            *(float2*)(outF + (size_t)gm * NDIM + gn) = o0;
            *(float2*)(outF + (size_t)(gm + 8) * NDIM + gn) = o1;
        }
    }
}

// ---------------------------------------------------------------- softmax
__global__ __launch_bounds__(256) void softmax_kernel(
    const float* __restrict__ p, float* __restrict__ out)
{
    const int row  = blockIdx.x * 8 + (threadIdx.x >> 5);
    const int lane = threadIdx.x & 31;
    const float* pr = p + (size_t)row * NDIM;
    float v[8];
    float mx = -INFINITY;
    #pragma unroll
    for (int i = 0; i < 8; ++i) { v[i] = pr[lane + 32 * i]; mx = fmaxf(mx, v[i]); }
    #pragma unroll
    for (int o = 16; o > 0; o >>= 1) mx = fmaxf(mx, __shfl_xor_sync(~0u, mx, o));
    float s = 0.f;
    #pragma unroll
    for (int i = 0; i < 8; ++i) { v[i] = expf(v[i] - mx); s += v[i]; }
    #pragma unroll
    for (int o = 16; o > 0; o >>= 1) s += __shfl_xor_sync(~0u, s, o);
    const float inv = 1.0f / s;
    float* orow = out + (size_t)row * NDIM;
    #pragma unroll
    for (int i = 0; i < 8; ++i) orow[lane + 32 * i] = v[i] * inv;
}

// ---------------------------------------------------------------- launch
extern "C" void kernel_launch(void* const* d_in, const int* in_sizes, int n_in,
                              void* d_out, int out_size)
{
    const float* x   = (const float*)d_in[0];
    const float* Whx = (const float*)d_in[1];
    const float* Whh = (const float*)d_in[2];
    const float* Wph = (const float*)d_in[3];
    const float* bh  = (const float*)d_in[4];
    const float* bp  = (const float*)d_in[5];

    int8_t *whx1, *whx2, *whh1, *whh2, *wph1, *wph2;
    int8_t *xb1, *xb2, *h0b1, *h0b2, *h1b1, *h1b2;
    float *c, *p;
    int* maxbits;
    cudaGetSymbolAddress((void**)&whx1, g_WhxA1);
    cudaGetSymbolAddress((void**)&whx2, g_WhxA2);
    cudaGetSymbolAddress((void**)&whh1, g_WhhA1);
    cudaGetSymbolAddress((void**)&whh2, g_WhhA2);
    cudaGetSymbolAddress((void**)&wph1, g_WphA1);
    cudaGetSymbolAddress((void**)&wph2, g_WphA2);
    cudaGetSymbolAddress((void**)&xb1,  g_xB1);
    cudaGetSymbolAddress((void**)&xb2,  g_xB2);
    cudaGetSymbolAddress((void**)&h0b1, g_h0B1);
    cudaGetSymbolAddress((void**)&h0b2, g_h0B2);
    cudaGetSymbolAddress((void**)&h1b1, g_h1B1);
    cudaGetSymbolAddress((void**)&h1b2, g_h1B2);
    cudaGetSymbolAddress((void**)&c,    g_c);
    cudaGetSymbolAddress((void**)&p,    g_p);
    cudaGetSymbolAddress((void**)&maxbits, g_maxbits);

    cudaFuncSetAttribute(rnn_gemm, cudaFuncAttributeMaxDynamicSharedMemorySize,
                         SMEM_BYTES);

    // prep: reset -> maxabs -> quantize (3 launches total)
    reset_kernel<<<1, 32>>>();
    maxabs_kernel<<<dim3(2048, 4), 256>>>(Whx, Whh, Wph, x);
    quant_kernel<<<dim3((MDIM * KDIM + 255) / 256, 4), 256>>>(Whx, Whh, Wph, x);

    const dim3 grid(NDIM / BN, MDIM / BM);   // (8, 32) = 256 CTAs

    // c = Whx @ x
    rnn_gemm<<<grid, THREADS, SMEM_BYTES>>>(whx1, whx2, xb1, xb2,
                                            maxbits + 0, maxbits + 3,
                                            nullptr, nullptr, c,
                                            nullptr, nullptr, 0);

    // step 1: h1 = tanh(c + bh) (h0 = 0)
    first_step_kernel<<<(MDIM * NDIM + 255) / 256, 256>>>(c, bh, h0b1, h0b2);

    // steps 2..256
    int8_t *pb1 = h0b1, *pb2 = h0b2, *nb1 = h1b1, *nb2 = h1b2;
    for (int t = 1; t < NDIM; ++t) {
        rnn_gemm<<<grid, THREADS, SMEM_BYTES>>>(whh1, whh2, pb1, pb2,
                                                maxbits + 1, nullptr,
                                                c, bh, nullptr,
                                                nb1, nb2, 2);
        int8_t* tm;
        tm = pb1; pb1 = nb1; nb1 = tm;
        tm = pb2; pb2 = nb2; nb2 = tm;
    }

    // p = Wph @ h + bp; softmax
    rnn_gemm<<<grid, THREADS, SMEM_BYTES>>>(wph1, wph2, pb1, pb2,
                                            maxbits + 2, nullptr,
                                            nullptr, bp, p,
                                            nullptr, nullptr, 1);
    softmax_kernel<<<MDIM / 8, 256>>>(p, (float*)d_out);
}

// round 9
// speedup vs baseline: 1.2033x; 1.2033x over previous
#include <cuda_runtime.h>
#include <math.h>
#include <stdint.h>

// ---------------------------------------------------------------- dims
constexpr int MDIM = 2048, KDIM = 2048, NDIM = 256;

// ---------------------------------------------------------------- tiling
constexpr int BM = 64, BN = 64, BK = 64;     // 64 int8 k per stage
constexpr int NIT = KDIM / BK;               // 32
constexpr int THREADS = 256;                 // 8 warps: 2 (m) x 4 (n)
constexpr int STAGES = 5;
constexpr int PREF = 4;
constexpr int ROWB = 80;                     // padded row bytes
constexpr int TILE_B = 64 * ROWB;            // 5120 B per operand tile
constexpr int STAGE_BYTES = 4 * TILE_B;      // A1,A2,B1,B2 = 20480
constexpr int SM_STAGE0 = 1024;              // stages start here (mbars below)
constexpr int SMEM_BYTES = SM_STAGE0 + STAGES * STAGE_BYTES;   // 103424

// padded global blobs: [blk][kstage][64 rows][80 B]
constexpr int WBLOB = 32 * 32 * TILE_B;      // 5,242,880 per weight digit
constexpr int HBLOB = 4 * 32 * TILE_B;       // 655,360 per h/x digit

// ---------------------------------------------------------------- scratch
__device__ __align__(128) int8_t g_WhxA1[WBLOB];
__device__ __align__(128) int8_t g_WhxA2[WBLOB];
__device__ __align__(128) int8_t g_WhhA1[WBLOB];
__device__ __align__(128) int8_t g_WhhA2[WBLOB];
__device__ __align__(128) int8_t g_WphA1[WBLOB];
__device__ __align__(128) int8_t g_WphA2[WBLOB];
__device__ __align__(128) int8_t g_xB1[HBLOB];
__device__ __align__(128) int8_t g_xB2[HBLOB];
__device__ __align__(128) int8_t g_h0B1[HBLOB];
__device__ __align__(128) int8_t g_h0B2[HBLOB];
__device__ __align__(128) int8_t g_h1B1[HBLOB];
__device__ __align__(128) int8_t g_h1B2[HBLOB];
__device__ float g_c[MDIM * NDIM];
__device__ float g_p[MDIM * NDIM];
__device__ int   g_maxbits[4];               // maxabs of Whx, Whh, Wph, x

// ---------------------------------------------------------------- helpers
__device__ __forceinline__ uint32_t smem_u32(const void* p) {
    uint32_t a;
    asm("{ .reg .u64 t; cvta.to.shared.u64 t, %1; cvt.u32.u64 %0, t; }"
        : "=r"(a) : "l"(p));
    return a;
}

__device__ __forceinline__ void mma_s8(int* c, const uint32_t* a,
                                       const uint32_t* b) {
    asm volatile(
        "mma.sync.aligned.m16n8k32.row.col.s32.s8.s8.s32 "
        "{%0,%1,%2,%3}, {%4,%5,%6,%7}, {%8,%9}, {%0,%1,%2,%3};"
        : "+r"(c[0]), "+r"(c[1]), "+r"(c[2]), "+r"(c[3])
        : "r"(a[0]), "r"(a[1]), "r"(a[2]), "r"(a[3]), "r"(b[0]), "r"(b[1]));
}

__device__ __forceinline__ void ldsm_x4(uint32_t* r, uint32_t addr) {
    asm volatile("ldmatrix.sync.aligned.m8n8.x4.shared.b16 {%0,%1,%2,%3}, [%4];"
                 : "=r"(r[0]), "=r"(r[1]), "=r"(r[2]), "=r"(r[3]) : "r"(addr));
}

__device__ __forceinline__ void bulkcp(uint32_t sdst, const void* gsrc,
                                       uint32_t bytes, uint32_t mbar) {
    asm volatile(
        "cp.async.bulk.shared::cta.global.mbarrier::complete_tx::bytes "
        "[%0], [%1], %2, [%3];"
        :: "r"(sdst), "l"(gsrc), "r"(bytes), "r"(mbar) : "memory");
}

__device__ __forceinline__ void mbar_init(uint32_t mbar, uint32_t cnt) {
    asm volatile("mbarrier.init.shared.b64 [%0], %1;"
                 :: "r"(mbar), "r"(cnt) : "memory");
}

__device__ __forceinline__ void mbar_expect_tx(uint32_t mbar, uint32_t bytes) {
    asm volatile("mbarrier.arrive.expect_tx.shared.b64 _, [%0], %1;"
                 :: "r"(mbar), "r"(bytes) : "memory");
}

__device__ __forceinline__ void mbar_wait(uint32_t mb, uint32_t parity) {
    asm volatile(
        "{\n\t.reg .pred P;\n\t"
        "L0_%=:\n\t"
        "mbarrier.try_wait.parity.acquire.cta.shared::cta.b64 P, [%0], %1, 0x989680;\n\t"
        "@P bra.uni L1_%=;\n\t"
        "bra.uni L0_%=;\n\t"
        "L1_%=:\n\t}"
        :: "r"(mb), "r"(parity) : "memory");
}

// quantize q in [-127,127] to two int8 digits: q ~= d1 + d2/256
__device__ __forceinline__ void quant2(float q, int8_t& d1, int8_t& d2) {
    float b1 = rintf(q);
    float b2 = rintf((q - b1) * 256.0f);
    b2 = fminf(fmaxf(b2, -127.0f), 127.0f);
    d1 = (int8_t)(int)b1;
    d2 = (int8_t)(int)b2;
}

// ---------------------------------------------------------------- prep
__global__ void reset_kernel() {
    if (threadIdx.x < 4) g_maxbits[threadIdx.x] = 0;
}

__global__ void maxabs_kernel(const float* __restrict__ w0,
                              const float* __restrict__ w1,
                              const float* __restrict__ w2,
                              const float* __restrict__ x) {
    const int t = blockIdx.y;
    const float* src = (t == 0) ? w0 : (t == 1) ? w1 : (t == 2) ? w2 : x;
    const int len = (t == 3) ? KDIM * NDIM : MDIM * KDIM;
    float m = 0.0f;
    for (int i = blockIdx.x * 256 + threadIdx.x; i < len; i += 2048 * 256)
        m = fmaxf(m, fabsf(src[i]));
    #pragma unroll
    for (int o = 16; o > 0; o >>= 1)
        m = fmaxf(m, __shfl_xor_sync(~0u, m, o));
    if ((threadIdx.x & 31) == 0)
        atomicMax(&g_maxbits[t], __float_as_int(m));
}

// quantize into padded tile blobs
__global__ void quant_kernel(const float* __restrict__ w0,
                             const float* __restrict__ w1,
                             const float* __restrict__ w2,
                             const float* __restrict__ x) {
    const int t = blockIdx.y;
    const int len = (t == 3) ? KDIM * NDIM : MDIM * KDIM;
    const int i = blockIdx.x * 256 + threadIdx.x;
    if (i >= len) return;
    const float mx = fmaxf(__int_as_float(g_maxbits[t]), 1e-20f);
    const float iq = 127.0f / mx;
    int8_t d1, d2;
    if (t == 3) {
        // x[K][N] -> blob[(n>>6)*32 + (k>>6)][n&63][k&63]
        const int k = i / NDIM, n = i % NDIM;
        quant2(x[i] * iq, d1, d2);
        const size_t off = (size_t)((n >> 6) * 32 + (k >> 6)) * TILE_B +
                           (n & 63) * ROWB + (k & 63);
        g_xB1[off] = d1;
        g_xB2[off] = d2;
    } else {
        // W[M][K] -> blob[(m>>6)*32 + (k>>6)][m&63][k&63]
        const int m = i >> 11, k = i & 2047;
        const float* w = (t == 0) ? w0 : (t == 1) ? w1 : w2;
        int8_t* o1 = (t == 0) ? g_WhxA1 : (t == 1) ? g_WhhA1 : g_WphA1;
        int8_t* o2 = (t == 0) ? g_WhxA2 : (t == 1) ? g_WhhA2 : g_WphA2;
        quant2(w[i] * iq, d1, d2);
        const size_t off = (size_t)((m >> 6) * 32 + (k >> 6)) * TILE_B +
                           (m & 63) * ROWB + (k & 63);
        o1[off] = d1;
        o2[off] = d2;
    }
}

// step 1 (h0 = 0): h1 = tanh(c + bh), quantized into padded blob
__global__ void first_step_kernel(const float* __restrict__ c,
                                  const float* __restrict__ bh,
                                  int8_t* __restrict__ outB1,
                                  int8_t* __restrict__ outB2) {
    const int i = blockIdx.x * 256 + threadIdx.x;
    if (i >= MDIM * NDIM) return;
    const int n = i >> 11, m = i & 2047;
    const float v = tanhf(c[(size_t)m * NDIM + n] + bh[n]);
    int8_t d1, d2;
    quant2(v * 127.0f, d1, d2);
    const size_t off = (size_t)((n >> 6) * 32 + (m >> 6)) * TILE_B +
                       (n & 63) * ROWB + (m & 63);
    outB1[off] = d1;
    outB2[off] = d2;
}

// ---------------------------------------------------------------- main GEMM
// D = sA*sB*(A1@B1 + (A1@B2 + A2@B1)/256); A,B in padded tile blobs.
// mode 0: outF = D ([M][N] fp32)
// mode 1: outF = D + bias
// mode 2: v = tanh(D + addc + bias); quant2(v*127) into padded h blob
__global__ void __launch_bounds__(THREADS) rnn_gemm(
    const int8_t* __restrict__ A1, const int8_t* __restrict__ A2,
    const int8_t* __restrict__ B1, const int8_t* __restrict__ B2,
    const int* __restrict__ maxA, const int* __restrict__ maxB,
    const float* __restrict__ addc, const float* __restrict__ bias,
    float* __restrict__ outF,
    int8_t* __restrict__ outB1, int8_t* __restrict__ outB2,
    int mode)
{
    extern __shared__ __align__(16) char sm[];
    const uint32_t sbase = smem_u32(sm);
    const int tid  = threadIdx.x;
    const int lane = tid & 31;
    const int wid  = tid >> 5;
    const int wm0  = (wid & 1) * 32;     // 2 warps in m (32 rows each)
    const int wn0  = (wid >> 1) * 16;    // 4 warps in n (16 cols each)
    const int mblk = blockIdx.y;         // 0..31
    const int nblk = blockIdx.x;         // 0..3
    const int m0   = mblk * BM;
    const int n0   = nblk * BN;

    const float sa  = __int_as_float(*maxA) * (1.0f / 127.0f);
    const float sb  = maxB ? __int_as_float(*maxB) * (1.0f / 127.0f)
                           : (1.0f / 127.0f);
    const float sAB = sa * sb;

    int C1[2][2][4] = {};
    int C2[2][2][4] = {};

    // ldmatrix lane offsets (bytes) — validated mapping (R6)
    const uint32_t aoff = (uint32_t)((lane & 15) * ROWB + (lane >> 4) * 16);
    const uint32_t boff = (uint32_t)((lane & 7) * ROWB +
                                     ((lane >> 4) & 1) * 8 * ROWB +
                                     ((lane >> 3) & 1) * 16);

    // mbarriers: one per stage at sbase + s*8
    if (tid == 0) {
        #pragma unroll
        for (int s = 0; s < STAGES; ++s) mbar_init(sbase + s * 8, 1);
        asm volatile("fence.proxy.async.shared::cta;" ::: "memory");
    }
    __syncthreads();

    auto issue_stage = [&](int it) {
        const int s = it % STAGES;
        const uint32_t mb = sbase + s * 8;
        const uint32_t dst = sbase + SM_STAGE0 + s * STAGE_BYTES;
        mbar_expect_tx(mb, STAGE_BYTES);
        bulkcp(dst,              A1 + (size_t)(mblk * 32 + it) * TILE_B, TILE_B, mb);
        bulkcp(dst + TILE_B,     A2 + (size_t)(mblk * 32 + it) * TILE_B, TILE_B, mb);
        bulkcp(dst + 2 * TILE_B, B1 + (size_t)(nblk * 32 + it) * TILE_B, TILE_B, mb);
        bulkcp(dst + 3 * TILE_B, B2 + (size_t)(nblk * 32 + it) * TILE_B, TILE_B, mb);
    };

    if (tid == 0) {
        #pragma unroll
        for (int s = 0; s < PREF; ++s) issue_stage(s);
    }

    for (int it = 0; it < NIT; ++it) {
        __syncthreads();   // all reads of stage used at it-1 are done
        if (tid == 0 && it + PREF < NIT) issue_stage(it + PREF);
        mbar_wait(sbase + (it % STAGES) * 8, (uint32_t)((it / STAGES) & 1));

        const uint32_t st  = sbase + SM_STAGE0 + (it % STAGES) * STAGE_BYTES;
        const uint32_t sA1 = st;
        const uint32_t sA2 = st + TILE_B;
        const uint32_t sB1 = st + 2 * TILE_B;
        const uint32_t sB2 = st + 3 * TILE_B;

        #pragma unroll
        for (int kk = 0; kk < 2; ++kk) {
            const uint32_t kb = kk * 32;           // one k32 chunk
            uint32_t a1f[2][4], a2f[2][4], b1f[4], b2f[4];
            ldsm_x4(a1f[0], sA1 + (uint32_t)(wm0 * ROWB) + kb + aoff);
            ldsm_x4(a1f[1], sA1 + (uint32_t)((wm0 + 16) * ROWB) + kb + aoff);
            ldsm_x4(a2f[0], sA2 + (uint32_t)(wm0 * ROWB) + kb + aoff);
            ldsm_x4(a2f[1], sA2 + (uint32_t)((wm0 + 16) * ROWB) + kb + aoff);
            ldsm_x4(b1f, sB1 + (uint32_t)(wn0 * ROWB) + kb + boff);
            ldsm_x4(b2f, sB2 + (uint32_t)(wn0 * ROWB) + kb + boff);
            #pragma unroll
            for (int mt = 0; mt < 2; ++mt)
                #pragma unroll
                for (int nt = 0; nt < 2; ++nt) {
                    mma_s8(C1[mt][nt], a1f[mt], &b1f[nt * 2]);
                    mma_s8(C2[mt][nt], a1f[mt], &b2f[nt * 2]);
                    mma_s8(C2[mt][nt], a2f[mt], &b1f[nt * 2]);
                }
        }
    }

    // ------------------------------------------------------------ epilogue
    if (mode == 2) {
        __syncthreads();    // tiles no longer read; reuse smem
        int8_t* th = (int8_t*)sm + SM_STAGE0;              // [64 n][80]
        int8_t* tl = (int8_t*)sm + SM_STAGE0 + 64 * ROWB;  // [64 n][80]
        #pragma unroll
        for (int mt = 0; mt < 2; ++mt)
            #pragma unroll
            for (int nt = 0; nt < 2; ++nt) {
                const int lr = wm0 + mt * 16 + (lane >> 2);
                const int lc = wn0 + nt * 8 + 2 * (lane & 3);
                const int gm = m0 + lr, gn = n0 + lc;
                float2 c0 = *(const float2*)(addc + (size_t)gm * NDIM + gn);
                float2 c1 = *(const float2*)(addc + (size_t)(gm + 8) * NDIM + gn);
                float2 bv = *(const float2*)(bias + gn);
                float d00 = sAB * ((float)C1[mt][nt][0] + (float)C2[mt][nt][0] * (1.0f / 256.0f));
                float d01 = sAB * ((float)C1[mt][nt][1] + (float)C2[mt][nt][1] * (1.0f / 256.0f));
                float d10 = sAB * ((float)C1[mt][nt][2] + (float)C2[mt][nt][2] * (1.0f / 256.0f));
                float d11 = sAB * ((float)C1[mt][nt][3] + (float)C2[mt][nt][3] * (1.0f / 256.0f));
                float v00 = tanhf(d00 + c0.x + bv.x) * 127.0f;
                float v01 = tanhf(d01 + c0.y + bv.y) * 127.0f;
                float v10 = tanhf(d10 + c1.x + bv.x) * 127.0f;
                float v11 = tanhf(d11 + c1.y + bv.y) * 127.0f;
                int8_t h, l;
                quant2(v00, h, l); th[lc * ROWB + lr] = h;       tl[lc * ROWB + lr] = l;
                quant2(v01, h, l); th[(lc + 1) * ROWB + lr] = h; tl[(lc + 1) * ROWB + lr] = l;
                quant2(v10, h, l); th[lc * ROWB + lr + 8] = h;   tl[lc * ROWB + lr + 8] = l;
                quant2(v11, h, l); th[(lc + 1) * ROWB + lr + 8] = h;
                                   tl[(lc + 1) * ROWB + lr + 8] = l;
            }
        __syncthreads();
        // writeout: 64 rows x 4 chunks x 2 arrays = 512 uint4, 2 per thread
        const int arr = tid >> 7;
        const int rq  = tid & 127;
        const int8_t* src = arr ? tl : th;
        int8_t* dstb = arr ? outB2 : outB1;
        const size_t base = (size_t)(nblk * 32 + mblk) * TILE_B;
        #pragma unroll
        for (int j = 0; j < 2; ++j) {
            const int cid = rq + 128 * j;      // 0..255
            const int row = cid >> 2;          // local n
            const int q   = cid & 3;
            uint4 v = *(const uint4*)&src[row * ROWB + q * 16];
            *(uint4*)&dstb[base + row * ROWB + q * 16] = v;
        }
    } else {
        #pragma unroll
        for (int mt = 0; mt < 2; ++mt)
            #pragma unroll
            for (int nt = 0; nt < 2; ++nt) {
                const int lr = wm0 + mt * 16 + (lane >> 2);
                const int lc = wn0 + nt * 8 + 2 * (lane & 3);
                const int gm = m0 + lr, gn = n0 + lc;
                float bx = 0.f, by = 0.f;
                if (mode == 1) {
                    float2 bv = *(const float2*)(bias + gn);
                    bx = bv.x; by = bv.y;
                }
                float2 o0, o1;
                o0.x = sAB * ((float)C1[mt][nt][0] + (float)C2[mt][nt][0] * (1.0f / 256.0f)) + bx;
                o0.y = sAB * ((float)C1[mt][nt][1] + (float)C2[mt][nt][1] * (1.0f / 256.0f)) + by;
                o1.x = sAB * ((float)C1[mt][nt][2] + (float)C2[mt][nt][2] * (1.0f / 256.0f)) + bx;
                o1.y = sAB * ((float)C1[mt][nt][3] + (float)C2[mt][nt][3] * (1.0f / 256.0f)) + by;
                *(float2*)(outF + (size_t)gm * NDIM + gn) = o0;
                *(float2*)(outF + (size_t)(gm + 8) * NDIM + gn) = o1;
            }
    }
}

// ---------------------------------------------------------------- softmax
__global__ __launch_bounds__(256) void softmax_kernel(
    const float* __restrict__ p, float* __restrict__ out)
{
    const int row  = blockIdx.x * 8 + (threadIdx.x >> 5);
    const int lane = threadIdx.x & 31;
    const float* pr = p + (size_t)row * NDIM;
    float v[8];
    float mx = -INFINITY;
    #pragma unroll
    for (int i = 0; i < 8; ++i) { v[i] = pr[lane + 32 * i]; mx = fmaxf(mx, v[i]); }
    #pragma unroll
    for (int o = 16; o > 0; o >>= 1) mx = fmaxf(mx, __shfl_xor_sync(~0u, mx, o));
    float s = 0.f;
    #pragma unroll
    for (int i = 0; i < 8; ++i) { v[i] = expf(v[i] - mx); s += v[i]; }
    #pragma unroll
    for (int o = 16; o > 0; o >>= 1) s += __shfl_xor_sync(~0u, s, o);
    const float inv = 1.0f / s;
    float* orow = out + (size_t)row * NDIM;
    #pragma unroll
    for (int i = 0; i < 8; ++i) orow[lane + 32 * i] = v[i] * inv;
}

// ---------------------------------------------------------------- launch
extern "C" void kernel_launch(void* const* d_in, const int* in_sizes, int n_in,
                              void* d_out, int out_size)
{
    const float* x   = (const float*)d_in[0];
    const float* Whx = (const float*)d_in[1];
    const float* Whh = (const float*)d_in[2];
    const float* Wph = (const float*)d_in[3];
    const float* bh  = (const float*)d_in[4];
    const float* bp  = (const float*)d_in[5];

    int8_t *whx1, *whx2, *whh1, *whh2, *wph1, *wph2;
    int8_t *xb1, *xb2, *h0b1, *h0b2, *h1b1, *h1b2;
    float *c, *p;
    int* maxbits;
    cudaGetSymbolAddress((void**)&whx1, g_WhxA1);
    cudaGetSymbolAddress((void**)&whx2, g_WhxA2);
    cudaGetSymbolAddress((void**)&whh1, g_WhhA1);
    cudaGetSymbolAddress((void**)&whh2, g_WhhA2);
    cudaGetSymbolAddress((void**)&wph1, g_WphA1);
    cudaGetSymbolAddress((void**)&wph2, g_WphA2);
    cudaGetSymbolAddress((void**)&xb1,  g_xB1);
    cudaGetSymbolAddress((void**)&xb2,  g_xB2);
    cudaGetSymbolAddress((void**)&h0b1, g_h0B1);
    cudaGetSymbolAddress((void**)&h0b2, g_h0B2);
    cudaGetSymbolAddress((void**)&h1b1, g_h1B1);
    cudaGetSymbolAddress((void**)&h1b2, g_h1B2);
    cudaGetSymbolAddress((void**)&c,    g_c);
    cudaGetSymbolAddress((void**)&p,    g_p);
    cudaGetSymbolAddress((void**)&maxbits, g_maxbits);

    cudaFuncSetAttribute(rnn_gemm, cudaFuncAttributeMaxDynamicSharedMemorySize,
                         SMEM_BYTES);

    reset_kernel<<<1, 32>>>();
    maxabs_kernel<<<dim3(2048, 4), 256>>>(Whx, Whh, Wph, x);
    quant_kernel<<<dim3((MDIM * KDIM + 255) / 256, 4), 256>>>(Whx, Whh, Wph, x);

    const dim3 grid(NDIM / BN, MDIM / BM);   // (4, 32) = 128 CTAs

    // c = Whx @ x
    rnn_gemm<<<grid, THREADS, SMEM_BYTES>>>(whx1, whx2, xb1, xb2,
                                            maxbits + 0, maxbits + 3,
                                            nullptr, nullptr, c,
                                            nullptr, nullptr, 0);

    // step 1: h1 = tanh(c + bh) (h0 = 0)
    first_step_kernel<<<(MDIM * NDIM + 255) / 256, 256>>>(c, bh, h0b1, h0b2);

    // steps 2..256
    int8_t *pb1 = h0b1, *pb2 = h0b2, *nb1 = h1b1, *nb2 = h1b2;
    for (int t = 1; t < NDIM; ++t) {
        rnn_gemm<<<grid, THREADS, SMEM_BYTES>>>(whh1, whh2, pb1, pb2,
                                                maxbits + 1, nullptr,
                                                c, bh, nullptr,
                                                nb1, nb2, 2);
        int8_t* tm;
        tm = pb1; pb1 = nb1; nb1 = tm;
        tm = pb2; pb2 = nb2; nb2 = tm;
    }

    // p = Wph @ h + bp; softmax
    rnn_gemm<<<grid, THREADS, SMEM_BYTES>>>(wph1, wph2, pb1, pb2,
                                            maxbits + 2, nullptr,
                                            nullptr, bp, p,
                                            nullptr, nullptr, 1);
    softmax_kernel<<<MDIM / 8, 256>>>(p, (float*)d_out);
}

// round 10
// speedup vs baseline: 1.3670x; 1.1361x over previous
#include <cuda_runtime.h>
#include <math.h>
#include <stdint.h>

// ---------------------------------------------------------------- dims
constexpr int MDIM = 2048, KDIM = 2048, NDIM = 256;

// ---------------------------------------------------------------- tiling
constexpr int BM = 64, BN = 64;
constexpr int THREADS = 512;                 // 16 warps: 4 (m) x 4 (n)
constexpr int STAGES = 4;                    // ring of k128 super-stages
constexpr int PREF = 3;
constexpr int NIT = KDIM / 128;              // 16 outer iterations (k128 each)
constexpr int ROWB = 80;                     // padded row bytes
constexpr int TILE_B = 64 * ROWB;            // 5120 B per operand k64 tile
constexpr int SUB_B = 4 * TILE_B;            // one k64 group (A1,A2,B1,B2)
constexpr int STAGE_BYTES = 2 * SUB_B;       // k128 super-stage = 40960
constexpr int SM_STAGE0 = 1024;
constexpr int SMEM_BYTES = SM_STAGE0 + STAGES * STAGE_BYTES;   // 164864

// padded global blobs: [blk][k64-tile][64 rows][80 B]
constexpr int WBLOB = 32 * 32 * TILE_B;
constexpr int HBLOB = 4 * 32 * TILE_B;

// ---------------------------------------------------------------- scratch
__device__ __align__(128) int8_t g_WhxA1[WBLOB];
__device__ __align__(128) int8_t g_WhxA2[WBLOB];
__device__ __align__(128) int8_t g_WhhA1[WBLOB];
__device__ __align__(128) int8_t g_WhhA2[WBLOB];
__device__ __align__(128) int8_t g_WphA1[WBLOB];
__device__ __align__(128) int8_t g_WphA2[WBLOB];
__device__ __align__(128) int8_t g_xB1[HBLOB];
__device__ __align__(128) int8_t g_xB2[HBLOB];
__device__ __align__(128) int8_t g_h0B1[HBLOB];
__device__ __align__(128) int8_t g_h0B2[HBLOB];
__device__ __align__(128) int8_t g_h1B1[HBLOB];
__device__ __align__(128) int8_t g_h1B2[HBLOB];
__device__ float g_c[MDIM * NDIM];
__device__ float g_p[MDIM * NDIM];
__device__ int   g_maxbits[4];

// ---------------------------------------------------------------- helpers
__device__ __forceinline__ uint32_t smem_u32(const void* p) {
    uint32_t a;
    asm("{ .reg .u64 t; cvta.to.shared.u64 t, %1; cvt.u32.u64 %0, t; }"
        : "=r"(a) : "l"(p));
    return a;
}

__device__ __forceinline__ void mma_s8(int* c, const uint32_t* a,
                                       const uint32_t* b) {
    asm volatile(
        "mma.sync.aligned.m16n8k32.row.col.s32.s8.s8.s32 "
        "{%0,%1,%2,%3}, {%4,%5,%6,%7}, {%8,%9}, {%0,%1,%2,%3};"
        : "+r"(c[0]), "+r"(c[1]), "+r"(c[2]), "+r"(c[3])
        : "r"(a[0]), "r"(a[1]), "r"(a[2]), "r"(a[3]), "r"(b[0]), "r"(b[1]));
}

__device__ __forceinline__ void ldsm_x4(uint32_t* r, uint32_t addr) {
    asm volatile("ldmatrix.sync.aligned.m8n8.x4.shared.b16 {%0,%1,%2,%3}, [%4];"
                 : "=r"(r[0]), "=r"(r[1]), "=r"(r[2]), "=r"(r[3]) : "r"(addr));
}

__device__ __forceinline__ void bulkcp(uint32_t sdst, const void* gsrc,
                                       uint32_t bytes, uint32_t mbar) {
    asm volatile(
        "cp.async.bulk.shared::cta.global.mbarrier::complete_tx::bytes "
        "[%0], [%1], %2, [%3];"
        :: "r"(sdst), "l"(gsrc), "r"(bytes), "r"(mbar) : "memory");
}

__device__ __forceinline__ void mbar_init(uint32_t mbar, uint32_t cnt) {
    asm volatile("mbarrier.init.shared.b64 [%0], %1;"
                 :: "r"(mbar), "r"(cnt) : "memory");
}

__device__ __forceinline__ void mbar_expect_tx(uint32_t mbar, uint32_t bytes) {
    asm volatile("mbarrier.arrive.expect_tx.shared.b64 _, [%0], %1;"
                 :: "r"(mbar), "r"(bytes) : "memory");
}

__device__ __forceinline__ void mbar_wait(uint32_t mb, uint32_t parity) {
    asm volatile(
        "{\n\t.reg .pred P;\n\t"
        "L0_%=:\n\t"
        "mbarrier.try_wait.parity.acquire.cta.shared::cta.b64 P, [%0], %1, 0x989680;\n\t"
        "@P bra.uni L1_%=;\n\t"
        "bra.uni L0_%=;\n\t"
        "L1_%=:\n\t}"
        :: "r"(mb), "r"(parity) : "memory");
}

__device__ __forceinline__ void quant2(float q, int8_t& d1, int8_t& d2) {
    float b1 = rintf(q);
    float b2 = rintf((q - b1) * 256.0f);
    b2 = fminf(fmaxf(b2, -127.0f), 127.0f);
    d1 = (int8_t)(int)b1;
    d2 = (int8_t)(int)b2;
}

// ---------------------------------------------------------------- prep
__global__ void reset_kernel() {
    if (threadIdx.x < 4) g_maxbits[threadIdx.x] = 0;
}

__global__ void maxabs_kernel(const float* __restrict__ w0,
                              const float* __restrict__ w1,
                              const float* __restrict__ w2,
                              const float* __restrict__ x) {
    const int t = blockIdx.y;
    const float* src = (t == 0) ? w0 : (t == 1) ? w1 : (t == 2) ? w2 : x;
    const int len = (t == 3) ? KDIM * NDIM : MDIM * KDIM;
    float m = 0.0f;
    for (int i = blockIdx.x * 256 + threadIdx.x; i < len; i += 2048 * 256)
        m = fmaxf(m, fabsf(src[i]));
    #pragma unroll
    for (int o = 16; o > 0; o >>= 1)
        m = fmaxf(m, __shfl_xor_sync(~0u, m, o));
    if ((threadIdx.x & 31) == 0)
        atomicMax(&g_maxbits[t], __float_as_int(m));
}

__global__ void quant_kernel(const float* __restrict__ w0,
                             const float* __restrict__ w1,
                             const float* __restrict__ w2,
                             const float* __restrict__ x) {
    const int t = blockIdx.y;
    const int len = (t == 3) ? KDIM * NDIM : MDIM * KDIM;
    const int i = blockIdx.x * 256 + threadIdx.x;
    if (i >= len) return;
    const float mx = fmaxf(__int_as_float(g_maxbits[t]), 1e-20f);
    const float iq = 127.0f / mx;
    int8_t d1, d2;
    if (t == 3) {
        const int k = i / NDIM, n = i % NDIM;
        quant2(x[i] * iq, d1, d2);
        const size_t off = (size_t)((n >> 6) * 32 + (k >> 6)) * TILE_B +
                           (n & 63) * ROWB + (k & 63);
        g_xB1[off] = d1;
        g_xB2[off] = d2;
    } else {
        const int m = i >> 11, k = i & 2047;
        const float* w = (t == 0) ? w0 : (t == 1) ? w1 : w2;
        int8_t* o1 = (t == 0) ? g_WhxA1 : (t == 1) ? g_WhhA1 : g_WphA1;
        int8_t* o2 = (t == 0) ? g_WhxA2 : (t == 1) ? g_WhhA2 : g_WphA2;
        quant2(w[i] * iq, d1, d2);
        const size_t off = (size_t)((m >> 6) * 32 + (k >> 6)) * TILE_B +
                           (m & 63) * ROWB + (k & 63);
        o1[off] = d1;
        o2[off] = d2;
    }
}

__global__ void first_step_kernel(const float* __restrict__ c,
                                  const float* __restrict__ bh,
                                  int8_t* __restrict__ outB1,
                                  int8_t* __restrict__ outB2) {
    const int i = blockIdx.x * 256 + threadIdx.x;
    if (i >= MDIM * NDIM) return;
    const int n = i >> 11, m = i & 2047;
    const float v = tanhf(c[(size_t)m * NDIM + n] + bh[n]);
    int8_t d1, d2;
    quant2(v * 127.0f, d1, d2);
    const size_t off = (size_t)((n >> 6) * 32 + (m >> 6)) * TILE_B +
                       (n & 63) * ROWB + (m & 63);
    outB1[off] = d1;
    outB2[off] = d2;
}

// ---------------------------------------------------------------- main GEMM
__global__ void __launch_bounds__(THREADS) rnn_gemm(
    const int8_t* __restrict__ A1, const int8_t* __restrict__ A2,
    const int8_t* __restrict__ B1, const int8_t* __restrict__ B2,
    const int* __restrict__ maxA, const int* __restrict__ maxB,
    const float* __restrict__ addc, const float* __restrict__ bias,
    float* __restrict__ outF,
    int8_t* __restrict__ outB1, int8_t* __restrict__ outB2,
    int mode)
{
    extern __shared__ __align__(16) char sm[];
    const uint32_t sbase = smem_u32(sm);
    const int tid  = threadIdx.x;
    const int lane = tid & 31;
    const int wid  = tid >> 5;
    const int wm0  = (wid & 3) * 16;     // 4 warps in m (16 rows each)
    const int wn0  = (wid >> 2) * 16;    // 4 warps in n (16 cols each)
    const int mblk = blockIdx.y;         // 0..31
    const int nblk = blockIdx.x;         // 0..3
    const int m0   = mblk * BM;
    const int n0   = nblk * BN;

    const float sa  = __int_as_float(*maxA) * (1.0f / 127.0f);
    const float sb  = maxB ? __int_as_float(*maxB) * (1.0f / 127.0f)
                           : (1.0f / 127.0f);
    const float sAB = sa * sb;

    int C1[2][4] = {};
    int C2[2][4] = {};

    const uint32_t aoff = (uint32_t)((lane & 15) * ROWB + (lane >> 4) * 16);
    const uint32_t boff = (uint32_t)((lane & 7) * ROWB +
                                     ((lane >> 4) & 1) * 8 * ROWB +
                                     ((lane >> 3) & 1) * 16);

    if (tid == 0) {
        #pragma unroll
        for (int s = 0; s < STAGES; ++s) mbar_init(sbase + s * 8, 1);
        asm volatile("fence.proxy.async.shared::cta;" ::: "memory");
    }
    __syncthreads();

    // one super-stage = two consecutive k64 tiles (8 bulk copies, 40 KB)
    auto issue_stage = [&](int it) {
        const int s = it % STAGES;
        const uint32_t mb = sbase + s * 8;
        const uint32_t dst = sbase + SM_STAGE0 + s * STAGE_BYTES;
        mbar_expect_tx(mb, STAGE_BYTES);
        #pragma unroll
        for (int h = 0; h < 2; ++h) {
            const int kt = 2 * it + h;
            const uint32_t d = dst + h * SUB_B;
            bulkcp(d,              A1 + (size_t)(mblk * 32 + kt) * TILE_B, TILE_B, mb);
            bulkcp(d + TILE_B,     A2 + (size_t)(mblk * 32 + kt) * TILE_B, TILE_B, mb);
            bulkcp(d + 2 * TILE_B, B1 + (size_t)(nblk * 32 + kt) * TILE_B, TILE_B, mb);
            bulkcp(d + 3 * TILE_B, B2 + (size_t)(nblk * 32 + kt) * TILE_B, TILE_B, mb);
        }
    };

    if (tid == 0) {
        #pragma unroll
        for (int s = 0; s < PREF; ++s) issue_stage(s);
    }

    for (int it = 0; it < NIT; ++it) {
        __syncthreads();   // all warps done reading the stage being reissued
        if (tid == 0 && it + PREF < NIT) issue_stage(it + PREF);
        mbar_wait(sbase + (it % STAGES) * 8, (uint32_t)((it / STAGES) & 1));

        const uint32_t st = sbase + SM_STAGE0 + (it % STAGES) * STAGE_BYTES;
        #pragma unroll
        for (int h = 0; h < 2; ++h) {
            const uint32_t sub = st + h * SUB_B;
            const uint32_t sA1 = sub;
            const uint32_t sA2 = sub + TILE_B;
            const uint32_t sB1 = sub + 2 * TILE_B;
            const uint32_t sB2 = sub + 3 * TILE_B;
            #pragma unroll
            for (int kk = 0; kk < 2; ++kk) {
                const uint32_t kb = kk * 32;
                uint32_t a1f[4], a2f[4], b1f[4], b2f[4];
                ldsm_x4(a1f, sA1 + (uint32_t)(wm0 * ROWB) + kb + aoff);
                ldsm_x4(a2f, sA2 + (uint32_t)(wm0 * ROWB) + kb + aoff);
                ldsm_x4(b1f, sB1 + (uint32_t)(wn0 * ROWB) + kb + boff);
                ldsm_x4(b2f, sB2 + (uint32_t)(wn0 * ROWB) + kb + boff);
                #pragma unroll
                for (int nt = 0; nt < 2; ++nt) {
                    mma_s8(C1[nt], a1f, &b1f[nt * 2]);
                    mma_s8(C2[nt], a1f, &b2f[nt * 2]);
                    mma_s8(C2[nt], a2f, &b1f[nt * 2]);
                }
            }
        }
    }

    // ------------------------------------------------------------ epilogue
    if (mode == 2) {
        __syncthreads();
        int8_t* th = (int8_t*)sm + SM_STAGE0;              // [64 n][80]
        int8_t* tl = (int8_t*)sm + SM_STAGE0 + 64 * ROWB;  // [64 n][80]
        #pragma unroll
        for (int nt = 0; nt < 2; ++nt) {
            const int lr = wm0 + (lane >> 2);
            const int lc = wn0 + nt * 8 + 2 * (lane & 3);
            const int gm = m0 + lr, gn = n0 + lc;
            float2 c0 = *(const float2*)(addc + (size_t)gm * NDIM + gn);
            float2 c1 = *(const float2*)(addc + (size_t)(gm + 8) * NDIM + gn);
            float2 bv = *(const float2*)(bias + gn);
            float d00 = sAB * ((float)C1[nt][0] + (float)C2[nt][0] * (1.0f / 256.0f));
            float d01 = sAB * ((float)C1[nt][1] + (float)C2[nt][1] * (1.0f / 256.0f));
            float d10 = sAB * ((float)C1[nt][2] + (float)C2[nt][2] * (1.0f / 256.0f));
            float d11 = sAB * ((float)C1[nt][3] + (float)C2[nt][3] * (1.0f / 256.0f));
            float v00 = tanhf(d00 + c0.x + bv.x) * 127.0f;
            float v01 = tanhf(d01 + c0.y + bv.y) * 127.0f;
            float v10 = tanhf(d10 + c1.x + bv.x) * 127.0f;
            float v11 = tanhf(d11 + c1.y + bv.y) * 127.0f;
            int8_t h, l;
            quant2(v00, h, l); th[lc * ROWB + lr] = h;       tl[lc * ROWB + lr] = l;
            quant2(v01, h, l); th[(lc + 1) * ROWB + lr] = h; tl[(lc + 1) * ROWB + lr] = l;
            quant2(v10, h, l); th[lc * ROWB + lr + 8] = h;   tl[lc * ROWB + lr + 8] = l;
            quant2(v11, h, l); th[(lc + 1) * ROWB + lr + 8] = h;
                               tl[(lc + 1) * ROWB + lr + 8] = l;
        }
        __syncthreads();
        // writeout: 2 arrays x 64 rows x 4 uint4 = 512 chunks, 1 per thread
        const int arr = tid >> 8;
        const int rq  = tid & 255;
        const int row = rq >> 2;
        const int q   = rq & 3;
        const int8_t* src = arr ? tl : th;
        int8_t* dstb = arr ? outB2 : outB1;
        const size_t base = (size_t)(nblk * 32 + mblk) * TILE_B;
        uint4 v = *(const uint4*)&src[row * ROWB + q * 16];
        *(uint4*)&dstb[base + row * ROWB + q * 16] = v;
    } else {
        #pragma unroll
        for (int nt = 0; nt < 2; ++nt) {
            const int lr = wm0 + (lane >> 2);
            const int lc = wn0 + nt * 8 + 2 * (lane & 3);
            const int gm = m0 + lr, gn = n0 + lc;
            float bx = 0.f, by = 0.f;
            if (mode == 1) {
                float2 bv = *(const float2*)(bias + gn);
                bx = bv.x; by = bv.y;
            }
            float2 o0, o1;
            o0.x = sAB * ((float)C1[nt][0] + (float)C2[nt][0] * (1.0f / 256.0f)) + bx;
            o0.y = sAB * ((float)C1[nt][1] + (float)C2[nt][1] * (1.0f / 256.0f)) + by;
            o1.x = sAB * ((float)C1[nt][2] + (float)C2[nt][2] * (1.0f / 256.0f)) + bx;
            o1.y = sAB * ((float)C1[nt][3] + (float)C2[nt][3] * (1.0f / 256.0f)) + by;
            *(float2*)(outF + (size_t)gm * NDIM + gn) = o0;
            *(float2*)(outF + (size_t)(gm + 8) * NDIM + gn) = o1;
        }
    }
}

// ---------------------------------------------------------------- softmax
__global__ __launch_bounds__(256) void softmax_kernel(
    const float* __restrict__ p, float* __restrict__ out)
{
    const int row  = blockIdx.x * 8 + (threadIdx.x >> 5);
    const int lane = threadIdx.x & 31;
    const float* pr = p + (size_t)row * NDIM;
    float v[8];
    float mx = -INFINITY;
    #pragma unroll
    for (int i = 0; i < 8; ++i) { v[i] = pr[lane + 32 * i]; mx = fmaxf(mx, v[i]); }
    #pragma unroll
    for (int o = 16; o > 0; o >>= 1) mx = fmaxf(mx, __shfl_xor_sync(~0u, mx, o));
    float s = 0.f;
    #pragma unroll
    for (int i = 0; i < 8; ++i) { v[i] = expf(v[i] - mx); s += v[i]; }
    #pragma unroll
    for (int o = 16; o > 0; o >>= 1) s += __shfl_xor_sync(~0u, s, o);
    const float inv = 1.0f / s;
    float* orow = out + (size_t)row * NDIM;
    #pragma unroll
    for (int i = 0; i < 8; ++i) orow[lane + 32 * i] = v[i] * inv;
}

// ---------------------------------------------------------------- launch
extern "C" void kernel_launch(void* const* d_in, const int* in_sizes, int n_in,
                              void* d_out, int out_size)
{
    const float* x   = (const float*)d_in[0];
    const float* Whx = (const float*)d_in[1];
    const float* Whh = (const float*)d_in[2];
    const float* Wph = (const float*)d_in[3];
    const float* bh  = (const float*)d_in[4];
    const float* bp  = (const float*)d_in[5];

    int8_t *whx1, *whx2, *whh1, *whh2, *wph1, *wph2;
    int8_t *xb1, *xb2, *h0b1, *h0b2, *h1b1, *h1b2;
    float *c, *p;
    int* maxbits;
    cudaGetSymbolAddress((void**)&whx1, g_WhxA1);
    cudaGetSymbolAddress((void**)&whx2, g_WhxA2);
    cudaGetSymbolAddress((void**)&whh1, g_WhhA1);
    cudaGetSymbolAddress((void**)&whh2, g_WhhA2);
    cudaGetSymbolAddress((void**)&wph1, g_WphA1);
    cudaGetSymbolAddress((void**)&wph2, g_WphA2);
    cudaGetSymbolAddress((void**)&xb1,  g_xB1);
    cudaGetSymbolAddress((void**)&xb2,  g_xB2);
    cudaGetSymbolAddress((void**)&h0b1, g_h0B1);
    cudaGetSymbolAddress((void**)&h0b2, g_h0B2);
    cudaGetSymbolAddress((void**)&h1b1, g_h1B1);
    cudaGetSymbolAddress((void**)&h1b2, g_h1B2);
    cudaGetSymbolAddress((void**)&c,    g_c);
    cudaGetSymbolAddress((void**)&p,    g_p);
    cudaGetSymbolAddress((void**)&maxbits, g_maxbits);

    cudaFuncSetAttribute(rnn_gemm, cudaFuncAttributeMaxDynamicSharedMemorySize,
                         SMEM_BYTES);

    reset_kernel<<<1, 32>>>();
    maxabs_kernel<<<dim3(2048, 4), 256>>>(Whx, Whh, Wph, x);
    quant_kernel<<<dim3((MDIM * KDIM + 255) / 256, 4), 256>>>(Whx, Whh, Wph, x);

    const dim3 grid(NDIM / BN, MDIM / BM);   // (4, 32) = 128 CTAs

    // c = Whx @ x
    rnn_gemm<<<grid, THREADS, SMEM_BYTES>>>(whx1, whx2, xb1, xb2,
                                            maxbits + 0, maxbits + 3,
                                            nullptr, nullptr, c,
                                            nullptr, nullptr, 0);

    // step 1: h1 = tanh(c + bh) (h0 = 0)
    first_step_kernel<<<(MDIM * NDIM + 255) / 256, 256>>>(c, bh, h0b1, h0b2);

    // steps 2..256
    int8_t *pb1 = h0b1, *pb2 = h0b2, *nb1 = h1b1, *nb2 = h1b2;
    for (int t = 1; t < NDIM; ++t) {
        rnn_gemm<<<grid, THREADS, SMEM_BYTES>>>(whh1, whh2, pb1, pb2,
                                                maxbits + 1, nullptr,
                                                c, bh, nullptr,
                                                nb1, nb2, 2);
        int8_t* tm;
        tm = pb1; pb1 = nb1; nb1 = tm;
        tm = pb2; pb2 = nb2; nb2 = tm;
    }

    // p = Wph @ h + bp; softmax
    rnn_gemm<<<grid, THREADS, SMEM_BYTES>>>(wph1, wph2, pb1, pb2,
                                            maxbits + 2, nullptr,
                                            nullptr, bp, p,
                                            nullptr, nullptr, 1);
    softmax_kernel<<<MDIM / 8, 256>>>(p, (float*)d_out);
}